// round 10
// baseline (speedup 1.0000x reference)
#include <cuda_runtime.h>
#include <cuda_bf16.h>

// Problem constants (fixed by the reference)
#define NN 4096
#define KK 32
#define DD 256
#define HH 128
#define GG 384   // 3*H
#define NR (NN + KK)   // h1 rows incl. one pad row per (possibly empty) cluster

typedef unsigned long long ull;

// ---------------- device scratch (no allocations allowed) ----------------
static __device__ float4 g_wih0p[64 * GG];   // W_ih0 packed [k4][g]
static __device__ float  g_xw0[NN * GG];     // x @ W_ih0^T + b_ih0
static __device__ float  g_xwz[GG];          // b_ih0 (zero-input row for empty clusters)
static __device__ float  g_h1[NR * HH];      // layer-0 hidden sequence
static __device__ float  g_xw1[NR * GG];     // h1 @ W_ih1^T + b_ih1
static __device__ int    g_sorted[NN];
static __device__ int    g_off[KK + 1];
static __device__ int    g_len[KK];
static __device__ float  g_emb[KK * HH];
static __device__ float  g_scores[NN];
static __device__ int    g_flagA[KK];        // per-cluster: h1 rows completed
static __device__ int    g_flagB[KK];        // per-cluster: xw1 rows completed

// ---------------- helpers ----------------
static __device__ __forceinline__ ull ffma2(ull a, ull b, ull c) {
    ull d;
    asm("fma.rn.f32x2 %0, %1, %2, %3;" : "=l"(d) : "l"(a), "l"(b), "l"(c));
    return d;
}
static __device__ __forceinline__ float f2sum(ull v) {
    float a, b;
    asm("mov.b64 {%0, %1}, %2;" : "=f"(a), "=f"(b) : "l"(v));
    return a + b;
}
static __device__ __forceinline__ float ex2_(float x) {
    float y; asm("ex2.approx.f32 %0, %1;" : "=f"(y) : "f"(x)); return y;
}
static __device__ __forceinline__ float rcp_(float x) {
    float y; asm("rcp.approx.f32 %0, %1;" : "=f"(y) : "f"(x)); return y;
}
#define L2E 1.4426950408889634f
static __device__ __forceinline__ float fast_sigmoid(float x) {
    return rcp_(1.0f + ex2_(-x * L2E));
}
static __device__ __forceinline__ float fast_tanh(float x) {
    x = fminf(x, 20.0f);
    float e = ex2_(x * (2.0f * L2E));
    return (e - 1.0f) * rcp_(e + 1.0f);
}
static __device__ __forceinline__ void bar_sync_n(int id, int cnt) {
    asm volatile("bar.sync %0, %1;" :: "r"(id), "r"(cnt) : "memory");
}
static __device__ __forceinline__ void bar_arrive_n(int id, int cnt) {
    asm volatile("bar.arrive %0, %1;" :: "r"(id), "r"(cnt) : "memory");
}
static __device__ __forceinline__ int ld_acquire(const int* p) {
    int v;
    asm volatile("ld.acquire.gpu.global.s32 %0, [%1];" : "=r"(v) : "l"(p) : "memory");
    return v;
}
static __device__ __forceinline__ void st_release(int* p, int v) {
    asm volatile("st.release.gpu.global.s32 [%0], %1;" :: "l"(p), "r"(v) : "memory");
}

// ---------------- kernel: cluster ordering (stable, parallel) ----------------
__global__ void k_setup(const int* __restrict__ labels) {
    __shared__ int ls[NN];
    __shared__ int cnt[8][KK];
    __shared__ int soff[8][KK];
    int t = threadIdx.x;                 // 256 threads
    if (t < KK) { g_flagA[t] = 0; g_flagB[t] = 0; }   // reset pipeline flags each run
    for (int i = t; i < NN; i += 256) ls[i] = labels[i];
    __syncthreads();
    int w = t >> 5, k = t & 31;
    {
        int c = 0;
        const int4* p = (const int4*)(ls + w * 512);
        for (int ii = 0; ii < 128; ++ii) {
            int4 v = p[ii];
            c += (v.x == k) + (v.y == k) + (v.z == k) + (v.w == k);
        }
        cnt[w][k] = c;
    }
    __syncthreads();
    if (w == 0) {
        int tot = 0;
        #pragma unroll
        for (int s = 0; s < 8; ++s) tot += cnt[s][k];
        g_len[k] = tot;
        int v = tot;
        #pragma unroll
        for (int d = 1; d < 32; d <<= 1) {
            int y = __shfl_up_sync(0xffffffffu, v, d);
            if (k >= d) v += y;
        }
        int off = v - tot;
        g_off[k] = off;
        if (k == 31) g_off[32] = off + tot;
        int run = off;
        #pragma unroll
        for (int s = 0; s < 8; ++s) { soff[s][k] = run; run += cnt[s][k]; }
    }
    __syncthreads();
    {
        int c = soff[w][k];
        const int4* p = (const int4*)(ls + w * 512);
        for (int ii = 0; ii < 128; ++ii) {
            int4 v = p[ii];
            int b = w * 512 + ii * 4;
            if (v.x == k) g_sorted[c++] = b;
            if (v.y == k) g_sorted[c++] = b + 1;
            if (v.z == k) g_sorted[c++] = b + 2;
            if (v.w == k) g_sorted[c++] = b + 3;
        }
    }
}

// ---------------- kernel: pack W_ih0 + zero-input row ----------------
__global__ void k_pack(const float* __restrict__ wih0, const float* __restrict__ b_ih0) {
    int k4 = blockIdx.x;         // 0..63
    int g  = threadIdx.x;        // 0..383
    const float* row = wih0 + (size_t)g * DD + k4 * 4;
    g_wih0p[k4 * GG + g] = make_float4(row[0], row[1], row[2], row[3]);
    if (k4 == 0) g_xwz[g] = b_ih0[g];
}

// ---------------- kernel: xw0 = x @ W_ih0^T + b_ih0 ----------------
__global__ void __launch_bounds__(384) k_xw0(const float* __restrict__ x,
                                             const float* __restrict__ b_ih0) {
    __shared__ __align__(16) float xs[16 * DD];   // 16 KB
    int r0 = blockIdx.x * 16;
    {
        const float4* xsrc = reinterpret_cast<const float4*>(x + (size_t)r0 * DD);
        float4* xd = reinterpret_cast<float4*>(xs);
        for (int i = threadIdx.x; i < 16 * DD / 4; i += 384) xd[i] = xsrc[i];
    }
    __syncthreads();
    int g = threadIdx.x;
    ull acc[16];
    #pragma unroll
    for (int s = 0; s < 16; ++s) acc[s] = 0ull;
    const ulonglong2* W = reinterpret_cast<const ulonglong2*>(g_wih0p) + g;
    #pragma unroll 8
    for (int k4 = 0; k4 < 64; ++k4) {
        ulonglong2 w = W[k4 * GG];
        #pragma unroll
        for (int s = 0; s < 16; ++s) {
            ulonglong2 xv = *reinterpret_cast<const ulonglong2*>(&xs[s * DD + k4 * 4]);
            acc[s] = ffma2(w.x, xv.x, acc[s]);
            acc[s] = ffma2(w.y, xv.y, acc[s]);
        }
    }
    float bi = b_ih0[g];
    #pragma unroll
    for (int s = 0; s < 16; ++s)
        g_xw0[(size_t)(r0 + s) * GG + g] = f2sum(acc[s]) + bi;
}

// ---------------- kernel: fused pipelined GRU (both layers + input GEMM) -----
// 96 CTAs, all co-resident (1 CTA/SM): per cluster c,
//   CTA c      (stage 0, producer): layer-0 recurrence -> g_h1 rows + flagA
//   CTA c+32   (stage 1, GEMM):     xw1[t] = W_ih1 @ h1[t] + b  -> g_xw1 + flagB
//   CTA c+64   (stage 2, consumer): layer-1 recurrence <- g_xw1  -> g_emb
// Stage i waits only on stage i-1 (acquire/release flags): deadlock-free.
// Thread t owns one 128-wide weight row in registers in every stage.
__global__ void __launch_bounds__(384, 1) k_rec2(
    const float* __restrict__ Whh0, const float* __restrict__ Wih1,
    const float* __restrict__ Whh1,
    const float* __restrict__ b_hh0, const float* __restrict__ b_ih1,
    const float* __restrict__ b_hh1) {
    __shared__ __align__(16) float h[HH];
    __shared__ float hw[GG];
    __shared__ __align__(16) float stage[64 * 132];   // 33.8 KB weight staging

    const int t = threadIdx.x;
    const int b = blockIdx.x;
    const int stg = b >> 5;          // 0 producer, 1 GEMM, 2 consumer
    const int c = b & 31;

    const float* Wsel = (stg == 0) ? Whh0 : (stg == 1) ? Wih1 : Whh1;
    const float* bsel = (stg == 0) ? b_hh0 : (stg == 1) ? b_ih1 : b_hh1;

    // ---- load weight row t into registers, smem-staged for coalescing
    ulonglong2 w[32];
    for (int grp = 0; grp < 6; ++grp) {
        const float4* src = reinterpret_cast<const float4*>(Wsel + (size_t)(64 * grp) * HH);
        #pragma unroll
        for (int u = 0; u < 6; ++u) {
            int f = t + u * 384;              // float4 index within 64x128 block
            if (f < 2048) {
                int r = f >> 5, c4 = f & 31;
                *(float4*)&stage[r * 132 + c4 * 4] = src[f];
            }
        }
        __syncthreads();
        if ((t >> 6) == grp) {
            int r = t & 63;
            #pragma unroll
            for (int i = 0; i < 32; ++i)
                w[i] = *(const ulonglong2*)&stage[r * 132 + i * 4];
        }
        __syncthreads();
    }
    float bias = bsel[t];

    const int len = g_len[c], off = g_off[c];
    const int len_e = max(len, 1);

    // ================= stage 1: streaming input GEMM =================
    if (stg == 1) {
        int fc = 0;
        for (int it = 0; it < len_e; ++it) {
            int row = (len > 0) ? (off + it) : (NN + c);
            if (fc <= it) { do { fc = ld_acquire(&g_flagA[c]); } while (fc <= it); }
            const ulonglong2* hr = reinterpret_cast<const ulonglong2*>(
                g_h1 + (size_t)row * HH);
            ull a0 = 0ull, a1 = 0ull, a2 = 0ull, a3 = 0ull;
            #pragma unroll
            for (int i = 0; i < 32; i += 2) {
                ulonglong2 hv0 = hr[i];
                ulonglong2 hv1 = hr[i + 1];
                a0 = ffma2(w[i].x,     hv0.x, a0);
                a1 = ffma2(w[i].y,     hv0.y, a1);
                a2 = ffma2(w[i + 1].x, hv1.x, a2);
                a3 = ffma2(w[i + 1].y, hv1.y, a3);
            }
            g_xw1[(size_t)row * GG + t] =
                (f2sum(a0) + f2sum(a1)) + (f2sum(a2) + f2sum(a3)) + bias;
            __syncthreads();
            if (t == 0) st_release(&g_flagB[c], it + 1);
        }
        return;
    }

    // ================= stages 0 & 2: recurrence =================
    if (t < HH) h[t] = 0.f;

    float xr = 0.f, xz = 0.f, xn = 0.f;
    int nidx = 0, fc = 0;
    if (t < HH) {
        if (stg == 0) {
            const float* r0 = (len > 0) ? (g_xw0 + (size_t)g_sorted[off] * GG) : g_xwz;
            xr = r0[t]; xz = r0[HH + t]; xn = r0[2 * HH + t];
            if (len > 1) nidx = g_sorted[off + 1];
        } else {
            do { fc = ld_acquire(&g_flagB[c]); } while (fc < 1);
            const float* r0 = g_xw1 + (size_t)((len > 0) ? off : (NN + c)) * GG;
            xr = r0[t]; xz = r0[HH + t]; xn = r0[2 * HH + t];
        }
    }
    __syncthreads();

    for (int it = 0; it < len_e; ++it) {
        // consumer: refresh flag cache early so the L2 acquire latency hides
        // under the matvec below
        if (stg == 2 && t < HH && fc < it + 2) fc = ld_acquire(&g_flagB[c]);

        // ---- matvec: row t dot h, 4 independent accumulation chains
        ull a0 = 0ull, a1 = 0ull, a2 = 0ull, a3 = 0ull;
        const ulonglong2* hp = reinterpret_cast<const ulonglong2*>(h);
        #pragma unroll
        for (int i = 0; i < 32; i += 2) {
            ulonglong2 hv0 = hp[i];
            ulonglong2 hv1 = hp[i + 1];
            a0 = ffma2(w[i].x,     hv0.x, a0);
            a1 = ffma2(w[i].y,     hv0.y, a1);
            a2 = ffma2(w[i + 1].x, hv1.x, a2);
            a3 = ffma2(w[i + 1].y, hv1.y, a3);
        }
        float myhw = (f2sum(a0) + f2sum(a1)) + (f2sum(a2) + f2sum(a3)) + bias;

        float r_pre = 0.f, hold = 0.f;
        if (t < HH) {
            // r-gate row is THIS thread's row: precompute r before the barrier
            r_pre = fast_sigmoid(xr + myhw);
            hold = h[t];
            bar_sync_n(1, 384);          // wait for z/n rows
        } else {
            hw[t] = myhw;                // z-rows (128..255), n-rows (256..383)
            bar_arrive_n(1, 384);        // non-blocking producer arrive
        }

        if (t < HH) {
            // prefetch next step's input row (latency hidden by gate math)
            float nxr = 0.f, nxz = 0.f, nxn = 0.f;
            bool more = (it + 1 < len_e);
            if (more) {
                const float* rn;
                if (stg == 0) {
                    rn = g_xw0 + (size_t)nidx * GG;
                } else {
                    while (fc < it + 2) fc = ld_acquire(&g_flagB[c]);
                    rn = g_xw1 + (size_t)(off + it + 1) * GG;
                }
                nxr = rn[t]; nxz = rn[HH + t]; nxn = rn[2 * HH + t];
                if (stg == 0 && it + 2 < len) nidx = g_sorted[off + it + 2];
            }
            // gates: r already computed; z and n MUFU chains overlap
            float z  = fast_sigmoid(xz + hw[HH + t]);
            float n  = fast_tanh(xn + r_pre * hw[2 * HH + t]);
            float hn = n + z * (hold - n);   // == (1-z)*n + z*h
            h[t] = hn;
            if (stg == 0) {
                int orow = (len > 0) ? (off + it) : (NN + c);
                g_h1[(size_t)orow * HH + t] = hn;
            }
            if (more) { xr = nxr; xz = nxz; xn = nxn; }
        }
        __syncthreads();   // h ready for next matvec; h1 stores drained
        if (stg == 0 && t == 0) st_release(&g_flagA[c], it + 1);
    }

    if (stg == 2 && t < HH) g_emb[c * HH + t] = h[t];
}

// ---------------- kernel: per-sentence tanh scores (weight-norm fused) -------
__global__ void __launch_bounds__(128) k_score(const float* __restrict__ x,
                                               const int* __restrict__ labels,
                                               const float* __restrict__ lin_v,
                                               const float* __restrict__ lin_g,
                                               const float* __restrict__ lin_b) {
    __shared__ __align__(16) float wns[GG];
    __shared__ __align__(16) float embs[KK][132];  // padded
    __shared__ float redw[4];
    int t = threadIdx.x;
    float v0 = lin_v[t], v1 = lin_v[HH + t], v2 = lin_v[2 * HH + t];
    float ss = v0 * v0 + v1 * v1 + v2 * v2;
    #pragma unroll
    for (int d = 16; d >= 1; d >>= 1) ss += __shfl_xor_sync(0xffffffffu, ss, d);
    if ((t & 31) == 0) redw[t >> 5] = ss;
    __syncthreads();
    float scale = lin_g[0] / sqrtf(redw[0] + redw[1] + redw[2] + redw[3]);
    wns[t] = v0 * scale; wns[HH + t] = v1 * scale; wns[2 * HH + t] = v2 * scale;
    for (int i = t; i < KK * HH; i += 128) embs[i >> 7][i & 127] = g_emb[i];
    __syncthreads();
    int i = blockIdx.x * 128 + t;
    int lab = labels[i];
    const float4* xr = reinterpret_cast<const float4*>(x) + (size_t)i * (DD / 4);
    float acc = 0.f;
    #pragma unroll 8
    for (int k4 = 0; k4 < DD / 4; ++k4) {
        float4 xv = xr[k4];
        float4 wv = *reinterpret_cast<const float4*>(&wns[k4 * 4]);
        acc = fmaf(xv.x, wv.x, acc); acc = fmaf(xv.y, wv.y, acc);
        acc = fmaf(xv.z, wv.z, acc); acc = fmaf(xv.w, wv.w, acc);
    }
    #pragma unroll 8
    for (int k4 = 0; k4 < HH / 4; ++k4) {
        float4 ev = *reinterpret_cast<const float4*>(&embs[lab][k4 * 4]);
        float4 wv = *reinterpret_cast<const float4*>(&wns[DD + k4 * 4]);
        acc = fmaf(ev.x, wv.x, acc); acc = fmaf(ev.y, wv.y, acc);
        acc = fmaf(ev.z, wv.z, acc); acc = fmaf(ev.w, wv.w, acc);
    }
    g_scores[i] = tanhf(acc + lin_b[0]);
}

// ---------------- kernel: fused per-cluster sum + final blend -----------------
__global__ void __launch_bounds__(128) k_sal(float* __restrict__ out) {
    __shared__ float red[128];
    int k = blockIdx.x;
    int len = g_len[k], off = g_off[k];
    float s = 0.f;
    for (int t = threadIdx.x; t < len; t += 128) s += g_scores[g_sorted[off + t]];
    red[threadIdx.x] = s;
    __syncthreads();
    #pragma unroll
    for (int d = 64; d >= 1; d >>= 1) {
        if (threadIdx.x < d) red[threadIdx.x] += red[threadIdx.x + d];
        __syncthreads();
    }
    float inv_sum = 1.0f / red[0];
    const float INV = 0.0625f;  // 1 / 4096^(1/3)
    for (int t = threadIdx.x; t < len; t += 128) {
        int i = g_sorted[off + t];
        float sal = g_scores[i] * inv_sum;
        float pos = fmaxf(0.5f, expf(-((float)(i + 1)) * INV));
        out[i] = 0.5f * sal + 0.5f * pos;
    }
}

// ---------------- launch ----------------
extern "C" void kernel_launch(void* const* d_in, const int* in_sizes, int n_in,
                              void* d_out, int out_size) {
    const float* x      = (const float*)d_in[0];
    const int*   labels = (const int*)d_in[1];
    const float* W_ih0  = (const float*)d_in[2];
    const float* W_hh0  = (const float*)d_in[3];
    const float* b_ih0  = (const float*)d_in[4];
    const float* b_hh0  = (const float*)d_in[5];
    const float* W_ih1  = (const float*)d_in[6];
    const float* W_hh1  = (const float*)d_in[7];
    const float* b_ih1  = (const float*)d_in[8];
    const float* b_hh1  = (const float*)d_in[9];
    const float* lin_v  = (const float*)d_in[10];
    const float* lin_g  = (const float*)d_in[11];
    const float* lin_b  = (const float*)d_in[12];
    float* out = (float*)d_out;

    k_setup<<<1, 256>>>(labels);
    k_pack<<<64, 384>>>(W_ih0, b_ih0);
    k_xw0<<<NN / 16, 384>>>(x, b_ih0);
    k_rec2<<<96, 384>>>(W_hh0, W_ih1, W_hh1, b_hh0, b_ih1, b_hh1);
    k_score<<<NN / 128, 128>>>(x, labels, lin_v, lin_g, lin_b);
    k_sal<<<KK, 128>>>(out);
}

// round 13
// speedup vs baseline: 1.0066x; 1.0066x over previous
#include <cuda_runtime.h>
#include <cuda_bf16.h>

// Problem constants (fixed by the reference)
#define NN 4096
#define KK 32
#define DD 256
#define HH 128
#define GG 384   // 3*H
#define NR (NN + KK)   // h1 rows incl. one pad row per (possibly empty) cluster

typedef unsigned long long ull;

// ---------------- device scratch (no allocations allowed) ----------------
static __device__ float4 g_wih0p[64 * GG];   // W_ih0 packed [k4][g]
static __device__ float  g_xw0[NN * GG];     // x @ W_ih0^T + b_ih0
static __device__ float  g_xwz[GG];          // b_ih0 (zero-input row for empty clusters)
static __device__ float  g_h1[NR * HH];      // layer-0 hidden sequence
static __device__ float  g_xw1[NR * GG];     // h1 @ W_ih1^T + b_ih1
static __device__ int    g_sorted[NN];
static __device__ int    g_off[KK + 1];
static __device__ int    g_len[KK];
static __device__ float  g_emb[KK * HH];
static __device__ float  g_scores[NN];
static __device__ int    g_flagA[KK];        // per-cluster: h1 rows completed
static __device__ int    g_flagB[KK];        // per-cluster: xw1 rows completed

// ---------------- helpers ----------------
static __device__ __forceinline__ ull ffma2(ull a, ull b, ull c) {
    ull d;
    asm("fma.rn.f32x2 %0, %1, %2, %3;" : "=l"(d) : "l"(a), "l"(b), "l"(c));
    return d;
}
static __device__ __forceinline__ float f2sum(ull v) {
    float a, b;
    asm("mov.b64 {%0, %1}, %2;" : "=f"(a), "=f"(b) : "l"(v));
    return a + b;
}
static __device__ __forceinline__ float ex2_(float x) {
    float y; asm("ex2.approx.f32 %0, %1;" : "=f"(y) : "f"(x)); return y;
}
static __device__ __forceinline__ float rcp_(float x) {
    float y; asm("rcp.approx.f32 %0, %1;" : "=f"(y) : "f"(x)); return y;
}
#define L2E 1.4426950408889634f
static __device__ __forceinline__ float fast_sigmoid(float x) {
    return rcp_(1.0f + ex2_(-x * L2E));
}
static __device__ __forceinline__ float fast_tanh(float x) {
    x = fminf(x, 20.0f);
    float e = ex2_(x * (2.0f * L2E));
    return (e - 1.0f) * rcp_(e + 1.0f);
}
static __device__ __forceinline__ void bar_sync_n(int id, int cnt) {
    asm volatile("bar.sync %0, %1;" :: "r"(id), "r"(cnt) : "memory");
}
static __device__ __forceinline__ void bar_arrive_n(int id, int cnt) {
    asm volatile("bar.arrive %0, %1;" :: "r"(id), "r"(cnt) : "memory");
}
static __device__ __forceinline__ int ld_acquire(const int* p) {
    int v;
    asm volatile("ld.acquire.gpu.global.s32 %0, [%1];" : "=r"(v) : "l"(p) : "memory");
    return v;
}
static __device__ __forceinline__ void st_release(int* p, int v) {
    asm volatile("st.release.gpu.global.s32 [%0], %1;" :: "l"(p), "r"(v) : "memory");
}

// ---------------- kernel: cluster ordering (stable, parallel) ----------------
__global__ void k_setup(const int* __restrict__ labels) {
    __shared__ int ls[NN];
    __shared__ int cnt[8][KK];
    __shared__ int soff[8][KK];
    int t = threadIdx.x;                 // 256 threads
    if (t < KK) { g_flagA[t] = 0; g_flagB[t] = 0; }   // reset pipeline flags each run
    for (int i = t; i < NN; i += 256) ls[i] = labels[i];
    __syncthreads();
    int w = t >> 5, k = t & 31;
    {
        int c = 0;
        const int4* p = (const int4*)(ls + w * 512);
        for (int ii = 0; ii < 128; ++ii) {
            int4 v = p[ii];
            c += (v.x == k) + (v.y == k) + (v.z == k) + (v.w == k);
        }
        cnt[w][k] = c;
    }
    __syncthreads();
    if (w == 0) {
        int tot = 0;
        #pragma unroll
        for (int s = 0; s < 8; ++s) tot += cnt[s][k];
        g_len[k] = tot;
        int v = tot;
        #pragma unroll
        for (int d = 1; d < 32; d <<= 1) {
            int y = __shfl_up_sync(0xffffffffu, v, d);
            if (k >= d) v += y;
        }
        int off = v - tot;
        g_off[k] = off;
        if (k == 31) g_off[32] = off + tot;
        int run = off;
        #pragma unroll
        for (int s = 0; s < 8; ++s) { soff[s][k] = run; run += cnt[s][k]; }
    }
    __syncthreads();
    {
        int c = soff[w][k];
        const int4* p = (const int4*)(ls + w * 512);
        for (int ii = 0; ii < 128; ++ii) {
            int4 v = p[ii];
            int b = w * 512 + ii * 4;
            if (v.x == k) g_sorted[c++] = b;
            if (v.y == k) g_sorted[c++] = b + 1;
            if (v.z == k) g_sorted[c++] = b + 2;
            if (v.w == k) g_sorted[c++] = b + 3;
        }
    }
}

// ---------------- kernel: pack W_ih0 + zero-input row ----------------
__global__ void k_pack(const float* __restrict__ wih0, const float* __restrict__ b_ih0) {
    int k4 = blockIdx.x;         // 0..63
    int g  = threadIdx.x;        // 0..383
    const float* row = wih0 + (size_t)g * DD + k4 * 4;
    g_wih0p[k4 * GG + g] = make_float4(row[0], row[1], row[2], row[3]);
    if (k4 == 0) g_xwz[g] = b_ih0[g];
}

// ---------------- kernel: xw0 = x @ W_ih0^T + b_ih0 ----------------
__global__ void __launch_bounds__(384) k_xw0(const float* __restrict__ x,
                                             const float* __restrict__ b_ih0) {
    __shared__ __align__(16) float xs[16 * DD];   // 16 KB
    int r0 = blockIdx.x * 16;
    {
        const float4* xsrc = reinterpret_cast<const float4*>(x + (size_t)r0 * DD);
        float4* xd = reinterpret_cast<float4*>(xs);
        for (int i = threadIdx.x; i < 16 * DD / 4; i += 384) xd[i] = xsrc[i];
    }
    __syncthreads();
    int g = threadIdx.x;
    ull acc[16];
    #pragma unroll
    for (int s = 0; s < 16; ++s) acc[s] = 0ull;
    const ulonglong2* W = reinterpret_cast<const ulonglong2*>(g_wih0p) + g;
    #pragma unroll 8
    for (int k4 = 0; k4 < 64; ++k4) {
        ulonglong2 w = W[k4 * GG];
        #pragma unroll
        for (int s = 0; s < 16; ++s) {
            ulonglong2 xv = *reinterpret_cast<const ulonglong2*>(&xs[s * DD + k4 * 4]);
            acc[s] = ffma2(w.x, xv.x, acc[s]);
            acc[s] = ffma2(w.y, xv.y, acc[s]);
        }
    }
    float bi = b_ih0[g];
    #pragma unroll
    for (int s = 0; s < 16; ++s)
        g_xw0[(size_t)(r0 + s) * GG + g] = f2sum(acc[s]) + bi;
}

// ---------------- kernel: fused pipelined GRU (both layers + input GEMM) -----
// 96 CTAs, all co-resident (1 CTA/SM): per cluster c,
//   CTA c      (stage 0, producer): layer-0 recurrence -> g_h1 rows + flagA
//   CTA c+32   (stage 1, GEMM):     xw1[t] = W_ih1 @ h1[t] + b  -> g_xw1 + flagB
//   CTA c+64   (stage 2, consumer): layer-1 recurrence <- g_xw1  -> g_emb
// CHUNKED handoff: flags released every 8 steps (and at the end), and the
// consumer polls LAZILY on a cached flag value -> the ld.acquire (which
// order-blocks all subsequent loads for ~260cyc) executes ~once per 8 steps
// instead of 1-2x per step (the R10 regression).
__global__ void __launch_bounds__(384, 1) k_rec2(
    const float* __restrict__ Whh0, const float* __restrict__ Wih1,
    const float* __restrict__ Whh1,
    const float* __restrict__ b_hh0, const float* __restrict__ b_ih1,
    const float* __restrict__ b_hh1) {
    __shared__ __align__(16) float h[HH];
    __shared__ float hw[GG];
    __shared__ __align__(16) float stage[64 * 132];   // 33.8 KB weight staging

    const int t = threadIdx.x;
    const int b = blockIdx.x;
    const int stg = b >> 5;          // 0 producer, 1 GEMM, 2 consumer
    const int c = b & 31;

    const float* Wsel = (stg == 0) ? Whh0 : (stg == 1) ? Wih1 : Whh1;
    const float* bsel = (stg == 0) ? b_hh0 : (stg == 1) ? b_ih1 : b_hh1;

    // ---- load weight row t into registers, smem-staged for coalescing
    ulonglong2 w[32];
    for (int grp = 0; grp < 6; ++grp) {
        const float4* src = reinterpret_cast<const float4*>(Wsel + (size_t)(64 * grp) * HH);
        #pragma unroll
        for (int u = 0; u < 6; ++u) {
            int f = t + u * 384;              // float4 index within 64x128 block
            if (f < 2048) {
                int r = f >> 5, c4 = f & 31;
                *(float4*)&stage[r * 132 + c4 * 4] = src[f];
            }
        }
        __syncthreads();
        if ((t >> 6) == grp) {
            int r = t & 63;
            #pragma unroll
            for (int i = 0; i < 32; ++i)
                w[i] = *(const ulonglong2*)&stage[r * 132 + i * 4];
        }
        __syncthreads();
    }
    float bias = bsel[t];

    const int len = g_len[c], off = g_off[c];
    const int len_e = max(len, 1);

    // ================= stage 1: streaming input GEMM =================
    if (stg == 1) {
        int fc = 0;
        for (int it = 0; it < len_e; ++it) {
            int row = (len > 0) ? (off + it) : (NN + c);
            if (fc <= it) { do { fc = ld_acquire(&g_flagA[c]); } while (fc <= it); }
            const ulonglong2* hr = reinterpret_cast<const ulonglong2*>(
                g_h1 + (size_t)row * HH);
            ull a0 = 0ull, a1 = 0ull, a2 = 0ull, a3 = 0ull;
            #pragma unroll
            for (int i = 0; i < 32; i += 2) {
                ulonglong2 hv0 = hr[i];
                ulonglong2 hv1 = hr[i + 1];
                a0 = ffma2(w[i].x,     hv0.x, a0);
                a1 = ffma2(w[i].y,     hv0.y, a1);
                a2 = ffma2(w[i + 1].x, hv1.x, a2);
                a3 = ffma2(w[i + 1].y, hv1.y, a3);
            }
            g_xw1[(size_t)row * GG + t] =
                (f2sum(a0) + f2sum(a1)) + (f2sum(a2) + f2sum(a3)) + bias;
            __syncthreads();
            if (t == 0 && ((((it + 1) & 7) == 0) || it == len_e - 1))
                st_release(&g_flagB[c], it + 1);
        }
        return;
    }

    // ================= stages 0 & 2: recurrence =================
    if (t < HH) h[t] = 0.f;

    float xr = 0.f, xz = 0.f, xn = 0.f;
    int nidx = 0, fc = 0;
    if (t < HH) {
        if (stg == 0) {
            const float* r0 = (len > 0) ? (g_xw0 + (size_t)g_sorted[off] * GG) : g_xwz;
            xr = r0[t]; xz = r0[HH + t]; xn = r0[2 * HH + t];
            if (len > 1) nidx = g_sorted[off + 1];
        } else {
            do { fc = ld_acquire(&g_flagB[c]); } while (fc < 1);
            const float* r0 = g_xw1 + (size_t)((len > 0) ? off : (NN + c)) * GG;
            xr = r0[t]; xz = r0[HH + t]; xn = r0[2 * HH + t];
        }
    }
    __syncthreads();

    for (int it = 0; it < len_e; ++it) {
        // ---- matvec: row t dot h, 4 independent accumulation chains
        ull a0 = 0ull, a1 = 0ull, a2 = 0ull, a3 = 0ull;
        const ulonglong2* hp = reinterpret_cast<const ulonglong2*>(h);
        #pragma unroll
        for (int i = 0; i < 32; i += 2) {
            ulonglong2 hv0 = hp[i];
            ulonglong2 hv1 = hp[i + 1];
            a0 = ffma2(w[i].x,     hv0.x, a0);
            a1 = ffma2(w[i].y,     hv0.y, a1);
            a2 = ffma2(w[i + 1].x, hv1.x, a2);
            a3 = ffma2(w[i + 1].y, hv1.y, a3);
        }
        float myhw = (f2sum(a0) + f2sum(a1)) + (f2sum(a2) + f2sum(a3)) + bias;

        float r_pre = 0.f, hold = 0.f;
        if (t < HH) {
            // r-gate row is THIS thread's row: precompute r before the barrier
            r_pre = fast_sigmoid(xr + myhw);
            hold = h[t];
            bar_sync_n(1, 384);          // wait for z/n rows
        } else {
            hw[t] = myhw;                // z-rows (128..255), n-rows (256..383)
            bar_arrive_n(1, 384);        // non-blocking producer arrive
        }

        if (t < HH) {
            // prefetch next step's input row (latency hidden by gate math)
            float nxr = 0.f, nxz = 0.f, nxn = 0.f;
            bool more = (it + 1 < len_e);
            if (more) {
                const float* rn;
                if (stg == 0) {
                    rn = g_xw0 + (size_t)nidx * GG;
                } else {
                    // lazy acquire: executes only when the cached flag is
                    // insufficient (~once per 8 steps with chunked releases)
                    if (fc < it + 2) {
                        do { fc = ld_acquire(&g_flagB[c]); } while (fc < it + 2);
                    }
                    rn = g_xw1 + (size_t)(off + it + 1) * GG;
                }
                nxr = rn[t]; nxz = rn[HH + t]; nxn = rn[2 * HH + t];
                if (stg == 0 && it + 2 < len) nidx = g_sorted[off + it + 2];
            }
            // gates: r already computed; z and n MUFU chains overlap
            float z  = fast_sigmoid(xz + hw[HH + t]);
            float n  = fast_tanh(xn + r_pre * hw[2 * HH + t]);
            float hn = n + z * (hold - n);   // == (1-z)*n + z*h
            h[t] = hn;
            if (stg == 0) {
                int orow = (len > 0) ? (off + it) : (NN + c);
                g_h1[(size_t)orow * HH + t] = hn;
            }
            if (more) { xr = nxr; xz = nxz; xn = nxn; }
        }
        __syncthreads();   // h ready for next matvec; h1 stores drained
        if (stg == 0 && t == 0 && ((((it + 1) & 7) == 0) || it == len_e - 1))
            st_release(&g_flagA[c], it + 1);
    }

    if (stg == 2 && t < HH) g_emb[c * HH + t] = h[t];
}

// ---------------- kernel: per-sentence tanh scores (weight-norm fused) -------
__global__ void __launch_bounds__(128) k_score(const float* __restrict__ x,
                                               const int* __restrict__ labels,
                                               const float* __restrict__ lin_v,
                                               const float* __restrict__ lin_g,
                                               const float* __restrict__ lin_b) {
    __shared__ __align__(16) float wns[GG];
    __shared__ __align__(16) float embs[KK][132];  // padded
    __shared__ float redw[4];
    int t = threadIdx.x;
    float v0 = lin_v[t], v1 = lin_v[HH + t], v2 = lin_v[2 * HH + t];
    float ss = v0 * v0 + v1 * v1 + v2 * v2;
    #pragma unroll
    for (int d = 16; d >= 1; d >>= 1) ss += __shfl_xor_sync(0xffffffffu, ss, d);
    if ((t & 31) == 0) redw[t >> 5] = ss;
    __syncthreads();
    float scale = lin_g[0] / sqrtf(redw[0] + redw[1] + redw[2] + redw[3]);
    wns[t] = v0 * scale; wns[HH + t] = v1 * scale; wns[2 * HH + t] = v2 * scale;
    for (int i = t; i < KK * HH; i += 128) embs[i >> 7][i & 127] = g_emb[i];
    __syncthreads();
    int i = blockIdx.x * 128 + t;
    int lab = labels[i];
    const float4* xr = reinterpret_cast<const float4*>(x) + (size_t)i * (DD / 4);
    float acc = 0.f;
    #pragma unroll 8
    for (int k4 = 0; k4 < DD / 4; ++k4) {
        float4 xv = xr[k4];
        float4 wv = *reinterpret_cast<const float4*>(&wns[k4 * 4]);
        acc = fmaf(xv.x, wv.x, acc); acc = fmaf(xv.y, wv.y, acc);
        acc = fmaf(xv.z, wv.z, acc); acc = fmaf(xv.w, wv.w, acc);
    }
    #pragma unroll 8
    for (int k4 = 0; k4 < HH / 4; ++k4) {
        float4 ev = *reinterpret_cast<const float4*>(&embs[lab][k4 * 4]);
        float4 wv = *reinterpret_cast<const float4*>(&wns[DD + k4 * 4]);
        acc = fmaf(ev.x, wv.x, acc); acc = fmaf(ev.y, wv.y, acc);
        acc = fmaf(ev.z, wv.z, acc); acc = fmaf(ev.w, wv.w, acc);
    }
    g_scores[i] = tanhf(acc + lin_b[0]);
}

// ---------------- kernel: fused per-cluster sum + final blend -----------------
__global__ void __launch_bounds__(128) k_sal(float* __restrict__ out) {
    __shared__ float red[128];
    int k = blockIdx.x;
    int len = g_len[k], off = g_off[k];
    float s = 0.f;
    for (int t = threadIdx.x; t < len; t += 128) s += g_scores[g_sorted[off + t]];
    red[threadIdx.x] = s;
    __syncthreads();
    #pragma unroll
    for (int d = 64; d >= 1; d >>= 1) {
        if (threadIdx.x < d) red[threadIdx.x] += red[threadIdx.x + d];
        __syncthreads();
    }
    float inv_sum = 1.0f / red[0];
    const float INV = 0.0625f;  // 1 / 4096^(1/3)
    for (int t = threadIdx.x; t < len; t += 128) {
        int i = g_sorted[off + t];
        float sal = g_scores[i] * inv_sum;
        float pos = fmaxf(0.5f, expf(-((float)(i + 1)) * INV));
        out[i] = 0.5f * sal + 0.5f * pos;
    }
}

// ---------------- launch ----------------
extern "C" void kernel_launch(void* const* d_in, const int* in_sizes, int n_in,
                              void* d_out, int out_size) {
    const float* x      = (const float*)d_in[0];
    const int*   labels = (const int*)d_in[1];
    const float* W_ih0  = (const float*)d_in[2];
    const float* W_hh0  = (const float*)d_in[3];
    const float* b_ih0  = (const float*)d_in[4];
    const float* b_hh0  = (const float*)d_in[5];
    const float* W_ih1  = (const float*)d_in[6];
    const float* W_hh1  = (const float*)d_in[7];
    const float* b_ih1  = (const float*)d_in[8];
    const float* b_hh1  = (const float*)d_in[9];
    const float* lin_v  = (const float*)d_in[10];
    const float* lin_g  = (const float*)d_in[11];
    const float* lin_b  = (const float*)d_in[12];
    float* out = (float*)d_out;

    k_setup<<<1, 256>>>(labels);
    k_pack<<<64, 384>>>(W_ih0, b_ih0);
    k_xw0<<<NN / 16, 384>>>(x, b_ih0);
    k_rec2<<<96, 384>>>(W_hh0, W_ih1, W_hh1, b_hh0, b_ih1, b_hh1);
    k_score<<<NN / 128, 128>>>(x, labels, lin_v, lin_g, lin_b);
    k_sal<<<KK, 128>>>(out);
}